// round 6
// baseline (speedup 1.0000x reference)
#include <cuda_runtime.h>
#include <math.h>

// Problem constants
#define E   4096
#define BB  8          // batch
#define TJ  256        // columns per block in K1 (256 threads * 1 col)
#define TK  32         // rows per split in K1
#define NSPLIT (E / TK)   // 128 row-splits
#define NCOLB  (E / TJ)   // 16 column blocks

// Deterministic split-K scratch: [NSPLIT][BB][E] fp32 = 16 MB
__device__ float g_scratch[(size_t)NSPLIT * BB * E];

// ---------------------------------------------------------------------------
// K1: stream w/alpha/hebb once (192 MB). Each block: 32 rows x 256 cols.
// 1 col/thread (scalar loads, fully coalesced 128B/warp/LDG).
// acc = 8 regs -> ~40 regs total -> 6 blocks/SM (75% occ), grid = 2048.
// ---------------------------------------------------------------------------
__global__ __launch_bounds__(256, 6)
void k1_partial_gemm(const float* __restrict__ yin,
                     const float* __restrict__ hebb,
                     const float* __restrict__ w,
                     const float* __restrict__ alpha)
{
    const int cb  = blockIdx.x;            // 0..NCOLB-1
    const int rb  = blockIdx.y;            // 0..NSPLIT-1
    const int tid = threadIdx.x;           // 0..255
    const int j   = cb * TJ + tid;         // this thread's column
    const int k0  = rb * TK;

    // Stage yin[b, k0:k0+TK] in smem (8*32 = 256 floats, one per thread)
    __shared__ float yin_s[BB][TK];
    {
        int b = tid / TK, k = tid % TK;    // tid < 256 = BB*TK exactly
        yin_s[b][k] = yin[(size_t)b * E + k0 + k];
    }
    __syncthreads();

    float acc[BB];
#pragma unroll
    for (int b = 0; b < BB; b++) acc[b] = 0.f;

    const float* wp = w     + (size_t)k0 * E + j;
    const float* ap = alpha + (size_t)k0 * E + j;
    const float* hp = hebb  + (size_t)k0 * E + j;

    // Depth-2 register pipeline: rows k and k+1 in flight
    float w0 = __ldcs(wp);
    float a0 = __ldcs(ap);
    float h0 = __ldg (hp);
    float w1 = __ldcs(wp + E);
    float a1 = __ldcs(ap + E);
    float h1 = __ldg (hp + E);

#pragma unroll 8
    for (int k = 0; k < TK; k++) {
        float wn, an, hn;
        if (k + 2 < TK) {
            const size_t off = (size_t)(k + 2) * E;
            wn = __ldcs(wp + off);
            an = __ldcs(ap + off);
            hn = __ldg (hp + off);
        }

        const float m = fmaf(a0, h0, w0);
#pragma unroll
        for (int b = 0; b < BB; b++)
            acc[b] = fmaf(yin_s[b][k], m, acc[b]);

        w0 = w1; a0 = a1; h0 = h1;
        w1 = wn; a1 = an; h1 = hn;
    }

#pragma unroll
    for (int b = 0; b < BB; b++)
        g_scratch[((size_t)rb * BB + b) * E + j] = acc[b];
}

// ---------------------------------------------------------------------------
// K2: reduce splits + input, tanh -> yout (written to d_out[0 : BB*E])
// ---------------------------------------------------------------------------
__global__ __launch_bounds__(256)
void k2_yout(const float* __restrict__ input, float* __restrict__ yout)
{
    const int idx = blockIdx.x * 256 + threadIdx.x;  // 0 .. BB*E-1
    if (idx >= BB * E) return;
    float s = input[idx];
#pragma unroll 8
    for (int r = 0; r < NSPLIT; r++)
        s += g_scratch[(size_t)r * BB * E + idx];
    yout[idx] = tanhf(s);
}

// ---------------------------------------------------------------------------
// K3: hebb_new = (1-eta)*hebb + eta * yin0 (outer) yout0   (128 MB stream)
// ---------------------------------------------------------------------------
__global__ __launch_bounds__(256)
void k3_hebb(const float* __restrict__ hebb,
             const float* __restrict__ yin,    // row 0 used
             const float* __restrict__ eta,    // scalar
             const float* __restrict__ yout0,  // d_out row 0 (E floats)
             float* __restrict__ hebb_out)
{
    const float et    = eta[0];
    const float one_m = 1.0f - et;

    const int t = blockIdx.x * 256 + threadIdx.x;     // one float4 per thread
    const int n4 = (E * E) / 4;
    if (t >= n4) return;

    const int row = t / (E / 4);
    const int c4  = t % (E / 4);
    const float s = et * yin[row];                    // eta * yin0[row]

    const float4 h = __ldcs((const float4*)(hebb + (size_t)t * 4));
    const float4 y = *(const float4*)(yout0 + (size_t)c4 * 4);
    float4 o;
    o.x = fmaf(one_m, h.x, s * y.x);
    o.y = fmaf(one_m, h.y, s * y.y);
    o.z = fmaf(one_m, h.z, s * y.z);
    o.w = fmaf(one_m, h.w, s * y.w);
    __stcs((float4*)(hebb_out + (size_t)t * 4), o);
}

// ---------------------------------------------------------------------------
// Launch: inputs in metadata order: input, yin, hebb, w, alpha, eta
// Output: [yout (8*4096) | hebb_new (4096*4096)] fp32
// ---------------------------------------------------------------------------
extern "C" void kernel_launch(void* const* d_in, const int* in_sizes, int n_in,
                              void* d_out, int out_size)
{
    const float* input = (const float*)d_in[0];
    const float* yin   = (const float*)d_in[1];
    const float* hebb  = (const float*)d_in[2];
    const float* w     = (const float*)d_in[3];
    const float* alpha = (const float*)d_in[4];
    const float* eta   = (const float*)d_in[5];

    float* out      = (float*)d_out;
    float* yout     = out;            // BB*E
    float* hebb_out = out + BB * E;   // E*E

    // K1: 16 col-blocks x 128 row-splits = 2048 blocks x 256 threads
    dim3 g1(NCOLB, NSPLIT);
    k1_partial_gemm<<<g1, 256>>>(yin, hebb, w, alpha);

    // K2: 32768 elems
    k2_yout<<<(BB * E + 255) / 256, 256>>>(input, yout);

    // K3: E*E/4 float4 threads
    const int n4 = (E * E) / 4;
    k3_hebb<<<(n4 + 255) / 256, 256>>>(hebb, yin, eta, yout, hebb_out);
}

// round 7
// speedup vs baseline: 1.1996x; 1.1996x over previous
#include <cuda_runtime.h>
#include <math.h>

// Problem constants
#define E   4096
#define BB  8          // batch
#define TJ  512        // columns per block in K1 (256 threads * float2)
#define TK  32         // rows per split in K1
#define NSPLIT (E / TK)   // 128 row-splits
#define NCOLB  (E / TJ)   // 8 column blocks

// Deterministic split-K scratch: [NSPLIT][BB][E] fp32 = 16 MB
__device__ float g_scratch[(size_t)NSPLIT * BB * E];

// ---------------------------------------------------------------------------
// K1: stream w/alpha/hebb once (192 MB). Each block: 32 rows x 512 cols.
// float2 loads (R5 sweet spot: 64 regs, low L1tex rate), grid=1024 to fill
// all 4-block/SM residency slots (R5 was grid-quantized at 512).
// ---------------------------------------------------------------------------
__global__ __launch_bounds__(256, 4)
void k1_partial_gemm(const float* __restrict__ yin,
                     const float* __restrict__ hebb,
                     const float* __restrict__ w,
                     const float* __restrict__ alpha)
{
    const int cb  = blockIdx.x;            // 0..NCOLB-1
    const int rb  = blockIdx.y;            // 0..NSPLIT-1
    const int tid = threadIdx.x;           // 0..255
    const int j0  = cb * TJ + tid * 2;     // this thread's 2 columns
    const int k0  = rb * TK;

    // Stage yin[b, k0:k0+TK] in smem (8*32 = 256 floats, one per thread)
    __shared__ float yin_s[BB][TK];
    {
        int b = tid / TK, k = tid % TK;    // tid < 256 = BB*TK exactly
        yin_s[b][k] = yin[(size_t)b * E + k0 + k];
    }
    __syncthreads();

    float accx[BB], accy[BB];
#pragma unroll
    for (int b = 0; b < BB; b++) { accx[b] = 0.f; accy[b] = 0.f; }

    const size_t base0 = (size_t)k0 * E + j0;
    const float2* wp = (const float2*)(w     + base0);
    const float2* ap = (const float2*)(alpha + base0);
    const float2* hp = (const float2*)(hebb  + base0);
    const int strideV = E / 2;             // float2 row stride

    // Depth-2 pipeline: rows k and k+1 in flight
    float2 w0 = __ldcs(wp);
    float2 a0 = __ldcs(ap);
    float2 h0 = __ldg (hp);
    float2 w1 = __ldcs(wp + strideV);
    float2 a1 = __ldcs(ap + strideV);
    float2 h1 = __ldg (hp + strideV);

#pragma unroll 8
    for (int k = 0; k < TK; k++) {
        float2 wn, an, hn;
        if (k + 2 < TK) {
            const int off = (k + 2) * strideV;
            wn = __ldcs(wp + off);
            an = __ldcs(ap + off);
            hn = __ldg (hp + off);
        }

        const float mx = fmaf(a0.x, h0.x, w0.x);
        const float my = fmaf(a0.y, h0.y, w0.y);
#pragma unroll
        for (int b = 0; b < BB; b++) {
            const float yv = yin_s[b][k];
            accx[b] = fmaf(yv, mx, accx[b]);
            accy[b] = fmaf(yv, my, accy[b]);
        }

        w0 = w1; a0 = a1; h0 = h1;
        w1 = wn; a1 = an; h1 = hn;
    }

    // Streaming stores: don't let scratch evict hebb from L2
#pragma unroll
    for (int b = 0; b < BB; b++) {
        float2 v = make_float2(accx[b], accy[b]);
        __stcs((float2*)(g_scratch + ((size_t)rb * BB + b) * E + j0), v);
    }
}

// ---------------------------------------------------------------------------
// K2: reduce splits + input, tanh -> yout (written to d_out[0 : BB*E])
// ---------------------------------------------------------------------------
__global__ __launch_bounds__(256)
void k2_yout(const float* __restrict__ input, float* __restrict__ yout)
{
    const int idx = blockIdx.x * 256 + threadIdx.x;  // 0 .. BB*E-1
    if (idx >= BB * E) return;
    float s = input[idx];
#pragma unroll 8
    for (int r = 0; r < NSPLIT; r++)
        s += __ldcs(&g_scratch[(size_t)r * BB * E + idx]);
    yout[idx] = tanhf(s);
}

// ---------------------------------------------------------------------------
// K3: hebb_new = (1-eta)*hebb + eta * yin0 (outer) yout0   (128 MB stream)
// hebb read WITHOUT streaming hint: hope for L2 hits from K1's cached read.
// ---------------------------------------------------------------------------
__global__ __launch_bounds__(256)
void k3_hebb(const float* __restrict__ hebb,
             const float* __restrict__ yin,    // row 0 used
             const float* __restrict__ eta,    // scalar
             const float* __restrict__ yout0,  // d_out row 0 (E floats)
             float* __restrict__ hebb_out)
{
    const float et    = eta[0];
    const float one_m = 1.0f - et;

    const int t = blockIdx.x * 256 + threadIdx.x;     // one float4 per thread
    const int n4 = (E * E) / 4;
    if (t >= n4) return;

    const int row = t / (E / 4);
    const int c4  = t % (E / 4);
    const float s = et * yin[row];                    // eta * yin0[row]

    const float4 h = *(const float4*)(hebb + (size_t)t * 4);
    const float4 y = *(const float4*)(yout0 + (size_t)c4 * 4);
    float4 o;
    o.x = fmaf(one_m, h.x, s * y.x);
    o.y = fmaf(one_m, h.y, s * y.y);
    o.z = fmaf(one_m, h.z, s * y.z);
    o.w = fmaf(one_m, h.w, s * y.w);
    __stcs((float4*)(hebb_out + (size_t)t * 4), o);
}

// ---------------------------------------------------------------------------
// Launch: inputs in metadata order: input, yin, hebb, w, alpha, eta
// Output: [yout (8*4096) | hebb_new (4096*4096)] fp32
// ---------------------------------------------------------------------------
extern "C" void kernel_launch(void* const* d_in, const int* in_sizes, int n_in,
                              void* d_out, int out_size)
{
    const float* input = (const float*)d_in[0];
    const float* yin   = (const float*)d_in[1];
    const float* hebb  = (const float*)d_in[2];
    const float* w     = (const float*)d_in[3];
    const float* alpha = (const float*)d_in[4];
    const float* eta   = (const float*)d_in[5];

    float* out      = (float*)d_out;
    float* yout     = out;            // BB*E
    float* hebb_out = out + BB * E;   // E*E

    // K1: 8 col-blocks x 128 row-splits = 1024 blocks x 256 threads
    dim3 g1(NCOLB, NSPLIT);
    k1_partial_gemm<<<g1, 256>>>(yin, hebb, w, alpha);

    // K2: 32768 elems
    k2_yout<<<(BB * E + 255) / 256, 256>>>(input, yout);

    // K3: E*E/4 float4 threads
    const int n4 = (E * E) / 4;
    k3_hebb<<<(n4 + 255) / 256, 256>>>(hebb, yin, eta, yout, hebb_out);
}

// round 8
// speedup vs baseline: 1.2001x; 1.0004x over previous
#include <cuda_runtime.h>
#include <math.h>

// Problem constants
#define E   4096
#define BB  8          // batch
#define TJ  256        // columns per block in K1 (128 float2 lanes)
#define TK  64         // rows per block (two groups of 32, reduced in smem)
#define TKH 32         // rows per group
#define NSPLIT (E / TK)   // 64 row-splits -> scratch stays 8 MB
#define NCOLB  (E / TJ)   // 16 column blocks

// Deterministic split-K scratch: [NSPLIT][BB][E] fp32 = 8 MB (L2-resident)
__device__ float g_scratch[(size_t)NSPLIT * BB * E];

// ---------------------------------------------------------------------------
// K1: stream w/alpha/hebb once (192 MB). Block: 64 rows x 256 cols,
// split into two 32-row groups x 128 float2-threads. Group 1's partial acc
// is added to group 0's through smem; one scratch write per block.
// 2x warp count vs R5/R7 at identical scratch size.
// ---------------------------------------------------------------------------
__global__ __launch_bounds__(256, 5)
void k1_partial_gemm(const float* __restrict__ yin,
                     const float* __restrict__ hebb,
                     const float* __restrict__ w,
                     const float* __restrict__ alpha)
{
    const int cb   = blockIdx.x;             // 0..NCOLB-1
    const int rb   = blockIdx.y;             // 0..NSPLIT-1
    const int tid  = threadIdx.x;            // 0..255
    const int ct   = tid & 127;              // col-thread within group
    const int grp  = tid >> 7;               // 0 or 1
    const int j0   = cb * TJ + ct * 2;       // this thread's 2 columns
    const int k0   = rb * TK + grp * TKH;    // this group's first row

    // Stage yin[b, rb*TK : rb*TK+64] in smem (8*64 = 512 floats)
    __shared__ float yin_s[BB * TK];
    for (int i = tid; i < BB * TK; i += 256) {
        int b = i / TK, k = i % TK;
        yin_s[i] = yin[(size_t)b * E + rb * TK + k];
    }
    __syncthreads();
    // This group's yin slice base: yin_s[b*TK + grp*TKH + k]
    const float* yin_g = yin_s + grp * TKH;

    float accx[BB], accy[BB];
#pragma unroll
    for (int b = 0; b < BB; b++) { accx[b] = 0.f; accy[b] = 0.f; }

    const size_t base0 = (size_t)k0 * E + j0;
    const float2* wp = (const float2*)(w     + base0);
    const float2* ap = (const float2*)(alpha + base0);
    const float2* hp = (const float2*)(hebb  + base0);
    const int strideV = E / 2;               // float2 row stride

#pragma unroll 8
    for (int k = 0; k < TKH; k++) {
        const int off = k * strideV;
        const float2 w2 = __ldcs(wp + off);
        const float2 a2 = __ldcs(ap + off);
        const float2 h2 = __ldg (hp + off);
        const float mx = fmaf(a2.x, h2.x, w2.x);
        const float my = fmaf(a2.y, h2.y, w2.y);
#pragma unroll
        for (int b = 0; b < BB; b++) {
            const float yv = yin_g[b * TK + k];
            accx[b] = fmaf(yv, mx, accx[b]);
            accy[b] = fmaf(yv, my, accy[b]);
        }
    }

    // Reduce group 1 into group 0 via smem
    __shared__ float2 red_s[BB][128];
    if (grp == 1) {
#pragma unroll
        for (int b = 0; b < BB; b++)
            red_s[b][ct] = make_float2(accx[b], accy[b]);
    }
    __syncthreads();
    if (grp == 0) {
#pragma unroll
        for (int b = 0; b < BB; b++) {
            const float2 r = red_s[b][ct];
            float2 v = make_float2(accx[b] + r.x, accy[b] + r.y);
            // normal cached store: 8 MB scratch stays L2-resident for K2
            *(float2*)(g_scratch + ((size_t)rb * BB + b) * E + j0) = v;
        }
    }
}

// ---------------------------------------------------------------------------
// K2: reduce splits + input, tanh -> yout (written to d_out[0 : BB*E])
// ---------------------------------------------------------------------------
__global__ __launch_bounds__(256)
void k2_yout(const float* __restrict__ input, float* __restrict__ yout)
{
    const int idx = blockIdx.x * 256 + threadIdx.x;  // 0 .. BB*E-1
    if (idx >= BB * E) return;
    float s = input[idx];
#pragma unroll 8
    for (int r = 0; r < NSPLIT; r++)
        s += g_scratch[(size_t)r * BB * E + idx];
    yout[idx] = tanhf(s);
}

// ---------------------------------------------------------------------------
// K3: hebb_new = (1-eta)*hebb + eta * yin0 (outer) yout0   (128 MB stream)
// ---------------------------------------------------------------------------
__global__ __launch_bounds__(256)
void k3_hebb(const float* __restrict__ hebb,
             const float* __restrict__ yin,    // row 0 used
             const float* __restrict__ eta,    // scalar
             const float* __restrict__ yout0,  // d_out row 0 (E floats)
             float* __restrict__ hebb_out)
{
    const float et    = eta[0];
    const float one_m = 1.0f - et;

    const int t = blockIdx.x * 256 + threadIdx.x;     // one float4 per thread
    const int n4 = (E * E) / 4;
    if (t >= n4) return;

    const int row = t / (E / 4);
    const int c4  = t % (E / 4);
    const float s = et * yin[row];                    // eta * yin0[row]

    const float4 h = __ldcs((const float4*)(hebb + (size_t)t * 4));
    const float4 y = *(const float4*)(yout0 + (size_t)c4 * 4);
    float4 o;
    o.x = fmaf(one_m, h.x, s * y.x);
    o.y = fmaf(one_m, h.y, s * y.y);
    o.z = fmaf(one_m, h.z, s * y.z);
    o.w = fmaf(one_m, h.w, s * y.w);
    __stcs((float4*)(hebb_out + (size_t)t * 4), o);
}

// ---------------------------------------------------------------------------
// Launch: inputs in metadata order: input, yin, hebb, w, alpha, eta
// Output: [yout (8*4096) | hebb_new (4096*4096)] fp32
// ---------------------------------------------------------------------------
extern "C" void kernel_launch(void* const* d_in, const int* in_sizes, int n_in,
                              void* d_out, int out_size)
{
    const float* input = (const float*)d_in[0];
    const float* yin   = (const float*)d_in[1];
    const float* hebb  = (const float*)d_in[2];
    const float* w     = (const float*)d_in[3];
    const float* alpha = (const float*)d_in[4];
    const float* eta   = (const float*)d_in[5];

    float* out      = (float*)d_out;
    float* yout     = out;            // BB*E
    float* hebb_out = out + BB * E;   // E*E

    // K1: 16 col-blocks x 64 row-splits = 1024 blocks x 256 threads
    dim3 g1(NCOLB, NSPLIT);
    k1_partial_gemm<<<g1, 256>>>(yin, hebb, w, alpha);

    // K2: 32768 elems
    k2_yout<<<(BB * E + 255) / 256, 256>>>(input, yout);

    // K3: E*E/4 float4 threads
    const int n4 = (E * E) / 4;
    k3_hebb<<<(n4 + 255) / 256, 256>>>(hebb, yin, eta, yout, hebb_out);
}

// round 9
// speedup vs baseline: 1.3120x; 1.0933x over previous
#include <cuda_runtime.h>
#include <math.h>

// Problem constants
#define E   4096
#define BB  8          // batch
#define TJ  512        // columns per block in K1 (256 threads * float2)
#define TK  64         // rows per split in K1
#define NSPLIT (E / TK)   // 64 row-splits
#define NCOLB  (E / TJ)   // 8 column blocks

// Deterministic split-K scratch: [NSPLIT][BB][E] fp32 = 8 MB (L2-resident)
__device__ float g_scratch[(size_t)NSPLIT * BB * E];

// ---------------------------------------------------------------------------
// K1 (R5 measured optimum): stream w/alpha/hebb once (192 MB).
// Block: 64 rows x 512 cols, float2/thread, 64 regs, 4 blocks/SM.
// w/alpha: __ldcs (evict-first) so hebb stays L2-resident for K3.
// ---------------------------------------------------------------------------
__global__ __launch_bounds__(256, 4)
void k1_partial_gemm(const float* __restrict__ yin,
                     const float* __restrict__ hebb,
                     const float* __restrict__ w,
                     const float* __restrict__ alpha)
{
    const int cb  = blockIdx.x;            // 0..NCOLB-1
    const int rb  = blockIdx.y;            // 0..NSPLIT-1
    const int tid = threadIdx.x;           // 0..255
    const int j0  = cb * TJ + tid * 2;     // this thread's 2 columns
    const int k0  = rb * TK;

    // Stage yin[b, k0:k0+TK] in smem
    __shared__ float yin_s[BB][TK];
    for (int i = tid; i < BB * TK; i += 256) {
        int b = i / TK, k = i % TK;
        yin_s[b][k] = yin[(size_t)b * E + k0 + k];
    }
    __syncthreads();

    float accx[BB], accy[BB];
#pragma unroll
    for (int b = 0; b < BB; b++) { accx[b] = 0.f; accy[b] = 0.f; }

    const size_t base0 = (size_t)k0 * E + j0;
    const float2* wp = (const float2*)(w     + base0);
    const float2* ap = (const float2*)(alpha + base0);
    const float2* hp = (const float2*)(hebb  + base0);
    const int strideV = E / 2;             // float2 row stride

    // Depth-2 pipeline: rows k and k+1 in flight
    float2 w0 = __ldcs(wp);
    float2 a0 = __ldcs(ap);
    float2 h0 = __ldg (hp);
    float2 w1 = __ldcs(wp + strideV);
    float2 a1 = __ldcs(ap + strideV);
    float2 h1 = __ldg (hp + strideV);

#pragma unroll 8
    for (int k = 0; k < TK; k++) {
        float2 wn, an, hn;
        if (k + 2 < TK) {
            const int off = (k + 2) * strideV;
            wn = __ldcs(wp + off);
            an = __ldcs(ap + off);
            hn = __ldg (hp + off);
        }

        const float mx = fmaf(a0.x, h0.x, w0.x);
        const float my = fmaf(a0.y, h0.y, w0.y);
#pragma unroll
        for (int b = 0; b < BB; b++) {
            const float yv = yin_s[b][k];
            accx[b] = fmaf(yv, mx, accx[b]);
            accy[b] = fmaf(yv, my, accy[b]);
        }

        w0 = w1; a0 = a1; h0 = h1;
        w1 = wn; a1 = an; h1 = hn;
    }

    // Normal cached stores: 8 MB scratch stays L2-resident for K2
#pragma unroll
    for (int b = 0; b < BB; b++) {
        float2 v = make_float2(accx[b], accy[b]);
        *(float2*)(g_scratch + ((size_t)rb * BB + b) * E + j0) = v;
    }
}

// ---------------------------------------------------------------------------
// K2: reduce splits + input, tanh -> yout (written to d_out[0 : BB*E])
// ---------------------------------------------------------------------------
__global__ __launch_bounds__(256)
void k2_yout(const float* __restrict__ input, float* __restrict__ yout)
{
    const int idx = blockIdx.x * 256 + threadIdx.x;  // 0 .. BB*E-1
    if (idx >= BB * E) return;
    float s = input[idx];
#pragma unroll
    for (int r = 0; r < NSPLIT; r++)
        s += g_scratch[(size_t)r * BB * E + idx];
    yout[idx] = tanhf(s);
}

// ---------------------------------------------------------------------------
// K3: hebb_new = (1-eta)*hebb + eta * yin0 (outer) yout0.
// Blocks mapped in REVERSE so hebb is read MRU-first (K1's last wave wrote
// the high rows most recently -> those L2 lines are freshest). hebb_out is
// written with __stcs (evict-first) to avoid evicting not-yet-read hebb.
// ---------------------------------------------------------------------------
__global__ __launch_bounds__(256)
void k3_hebb(const float* __restrict__ hebb,
             const float* __restrict__ yin,    // row 0 used
             const float* __restrict__ eta,    // scalar
             const float* __restrict__ yout0,  // d_out row 0 (E floats)
             float* __restrict__ hebb_out)
{
    const float et    = eta[0];
    const float one_m = 1.0f - et;

    const int n4   = (E * E) / 4;
    const int rblk = gridDim.x - 1 - blockIdx.x;      // reverse block order
    const int t    = rblk * 256 + threadIdx.x;        // one float4 per thread
    if (t >= n4) return;

    const int row = t / (E / 4);
    const int c4  = t % (E / 4);
    const float s = et * yin[row];                    // eta * yin0[row]

    const float4 h = *(const float4*)(hebb + (size_t)t * 4);   // want L2 hits
    const float4 y = __ldg((const float4*)(yout0 + (size_t)c4 * 4));
    float4 o;
    o.x = fmaf(one_m, h.x, s * y.x);
    o.y = fmaf(one_m, h.y, s * y.y);
    o.z = fmaf(one_m, h.z, s * y.z);
    o.w = fmaf(one_m, h.w, s * y.w);
    __stcs((float4*)(hebb_out + (size_t)t * 4), o);
}

// ---------------------------------------------------------------------------
// Launch: inputs in metadata order: input, yin, hebb, w, alpha, eta
// Output: [yout (8*4096) | hebb_new (4096*4096)] fp32
// ---------------------------------------------------------------------------
extern "C" void kernel_launch(void* const* d_in, const int* in_sizes, int n_in,
                              void* d_out, int out_size)
{
    const float* input = (const float*)d_in[0];
    const float* yin   = (const float*)d_in[1];
    const float* hebb  = (const float*)d_in[2];
    const float* w     = (const float*)d_in[3];
    const float* alpha = (const float*)d_in[4];
    const float* eta   = (const float*)d_in[5];

    float* out      = (float*)d_out;
    float* yout     = out;            // BB*E
    float* hebb_out = out + BB * E;   // E*E

    // K1: 8 col-blocks x 64 row-splits = 512 blocks x 256 threads
    dim3 g1(NCOLB, NSPLIT);
    k1_partial_gemm<<<g1, 256>>>(yin, hebb, w, alpha);

    // K2: 32768 elems
    k2_yout<<<(BB * E + 255) / 256, 256>>>(input, yout);

    // K3: E*E/4 float4 threads, reverse-ordered blocks
    const int n4 = (E * E) / 4;
    k3_hebb<<<(n4 + 255) / 256, 256>>>(hebb, yin, eta, yout, hebb_out);
}